// round 17
// baseline (speedup 1.0000x reference)
#include <cuda_runtime.h>
#include <cuda_fp16.h>
#include <mma.h>
#include <math.h>
#include <stdint.h>

using namespace nvcuda;

#define NN 50000
#define NE 800000
#define F  128
#define MT 128        // rows per MMA block
#define HLD 136       // half leading dim for A/B smem
#define CLD 132       // float leading dim for C staging
#define SPAD 65       // scores transposed-tile pad
#define MMA_GRID    391
#define SCAT_GRID  3125   // NE/256 exactly
#define SCORES_GRID 782
#define AGG_GRID   6250

// ---------------- scratch (device globals; no allocation allowed) ----------
__device__ __align__(16) __half g_feath[NN * F];
__device__ __align__(16) float g_h1[NN * F];
__device__ __align__(16) float g_h2[NN * F];
__device__ __align__(16) float g_el[2][NN * 4];   // double-buffered scores
__device__ __align__(16) float g_er[2][NN * 4];
__device__ __align__(16) float g_wl[3][4 * F];    // W @ al[h], per layer
__device__ __align__(16) float g_wr[3][4 * F];    // W @ ar[h]
__device__ int g_rowptr[NN + 1];

// ---------------- wprep kernel: wl/wr for all 3 layers (block = slot) ------
__global__ __launch_bounds__(256) void wprep_kernel(
    const float* __restrict__ W0, const float* __restrict__ al0,
    const float* __restrict__ ar0,
    const float* __restrict__ W1, const float* __restrict__ al1,
    const float* __restrict__ ar1,
    const float* __restrict__ W2, const float* __restrict__ al2,
    const float* __restrict__ ar2)
{
    const int slot = blockIdx.x;
    const float* W  = (slot == 0) ? W0  : (slot == 1) ? W1  : W2;
    const float* al = (slot == 0) ? al0 : (slot == 1) ? al1 : al2;
    const float* ar = (slot == 0) ? ar0 : (slot == 1) ? ar1 : ar2;
    const int tid = threadIdx.x;
    #pragma unroll
    for (int j = 0; j < 4; j++) {
        int o = tid + 256 * j;                 // 1024 outputs
        int k = o & 127, hh = o >> 7, h = hh & 3;
        const float* vec = (hh < 4) ? al : ar;
        float s = 0.f;
        #pragma unroll
        for (int d = 0; d < 32; d++)
            s = fmaf(__ldg(&W[k * F + h * 32 + d]), __ldg(&vec[h * 32 + d]), s);
        if (hh < 4) g_wl[slot][h * F + k] = s; else g_wr[slot][h * F + k] = s;
    }
}

// ---------------- rowptr (scatter over sorted dst) + layer-0 scores --------
// Blocks [0, SCAT_GRID): thread e fills rowptr over gap (dst[e-1], dst[e]].
// Blocks beyond: 64 rows of el0/er0 from x via wl[0]/wr[0] (33KB smem).
extern __shared__ __align__(16) float s_hsT[];   // [F][SPAD]

__global__ __launch_bounds__(256) void rowptr_scores_kernel(
    const int* __restrict__ dst, const float* __restrict__ x)
{
    const int tid = threadIdx.x;
    if (blockIdx.x < SCAT_GRID) {
        int e = blockIdx.x * 256 + tid;
        int d1 = __ldg(&dst[e]);
        int d0 = (e == 0) ? -1 : __ldg(&dst[e - 1]);
        for (int n = d0 + 1; n <= d1; n++) g_rowptr[n] = e;
        if (e == NE - 1)
            for (int n = d1 + 1; n <= NN; n++) g_rowptr[n] = NE;
        return;
    }

    // scores path: el0/er0 for 64 rows of x
    const int base = (blockIdx.x - SCAT_GRID) * 64;
    {
        const int k4 = tid & 31, r0 = tid >> 5;
        #pragma unroll
        for (int j = 0; j < 8; j++) {
            int r = r0 + 8 * j;
            int n = base + r;
            float4 v = (n < NN)
                ? __ldg(reinterpret_cast<const float4*>(&x[n * F + 4 * k4]))
                : make_float4(0.f, 0.f, 0.f, 0.f);
            s_hsT[(4 * k4 + 0) * SPAD + r] = v.x;
            s_hsT[(4 * k4 + 1) * SPAD + r] = v.y;
            s_hsT[(4 * k4 + 2) * SPAD + r] = v.z;
            s_hsT[(4 * k4 + 3) * SPAD + r] = v.w;
        }
    }
    __syncthreads();

    const int r  = tid & 63;
    const int hd = tid >> 6;
    const int n  = base + r;
    float el = 0.f, er = 0.f;
    const float4* wl4 = reinterpret_cast<const float4*>(g_wl[0]);
    const float4* wr4 = reinterpret_cast<const float4*>(g_wr[0]);
    #pragma unroll 8
    for (int k4 = 0; k4 < 32; k4++) {
        float4 wlv = __ldg(&wl4[hd * 32 + k4]);
        float4 wrv = __ldg(&wr4[hd * 32 + k4]);
        float h0 = s_hsT[(4 * k4 + 0) * SPAD + r];
        float h1 = s_hsT[(4 * k4 + 1) * SPAD + r];
        float h2 = s_hsT[(4 * k4 + 2) * SPAD + r];
        float h3 = s_hsT[(4 * k4 + 3) * SPAD + r];
        el = fmaf(h0, wlv.x, fmaf(h1, wlv.y, fmaf(h2, wlv.z, fmaf(h3, wlv.w, el))));
        er = fmaf(h0, wrv.x, fmaf(h1, wrv.y, fmaf(h2, wrv.z, fmaf(h3, wrv.w, er))));
    }
    if (n < NN) {
        g_el[0][n * 4 + hd] = el;
        g_er[0][n * 4 + hd] = er;
    }
}

// ---------------- fp16 WMMA GEMM (staged) -> fp16 feat ---------------------
extern __shared__ __align__(16) char s_raw[];

__global__ __launch_bounds__(256) void mma_kernel(
    const float* __restrict__ hin, const float* __restrict__ W)
{
    __half* As = reinterpret_cast<__half*>(s_raw);               // [128][HLD]
    __half* Bs = reinterpret_cast<__half*>(s_raw) + MT * HLD;    // [128][HLD]
    float*  Cs = reinterpret_cast<float*>(s_raw);                // [128][CLD]
    const int tid  = threadIdx.x;
    const int base = blockIdx.x * MT;

    #pragma unroll
    for (int i = 0; i < 16; i++) {
        int idx = tid + 256 * i;
        int row = idx >> 5, c4 = idx & 31;
        int n = base + row;
        float4 v = (n < NN)
            ? __ldg(reinterpret_cast<const float4*>(&hin[n * F + 4 * c4]))
            : make_float4(0.f, 0.f, 0.f, 0.f);
        __half2 a01 = __floats2half2_rn(v.x, v.y);
        __half2 a23 = __floats2half2_rn(v.z, v.w);
        uint2 pa;
        pa.x = *reinterpret_cast<unsigned*>(&a01);
        pa.y = *reinterpret_cast<unsigned*>(&a23);
        *reinterpret_cast<uint2*>(&As[row * HLD + 4 * c4]) = pa;

        float4 wv = __ldg(reinterpret_cast<const float4*>(&W[idx * 4]));
        __half2 b01 = __floats2half2_rn(wv.x, wv.y);
        __half2 b23 = __floats2half2_rn(wv.z, wv.w);
        uint2 pb;
        pb.x = *reinterpret_cast<unsigned*>(&b01);
        pb.y = *reinterpret_cast<unsigned*>(&b23);
        *reinterpret_cast<uint2*>(&Bs[row * HLD + 4 * c4]) = pb;
    }
    __syncthreads();

    const int w  = tid >> 5;
    const int wr = w & 3;       // rows 32*wr .. +31
    const int wc = w >> 2;      // cols 64*wc .. +63

    wmma::fragment<wmma::accumulator, 16, 16, 16, float> c[2][4];
    #pragma unroll
    for (int i = 0; i < 2; i++)
        #pragma unroll
        for (int j = 0; j < 4; j++) wmma::fill_fragment(c[i][j], 0.f);

    #pragma unroll
    for (int k = 0; k < 8; k++) {
        wmma::fragment<wmma::matrix_a, 16, 16, 16, __half, wmma::row_major> a[2];
        wmma::fragment<wmma::matrix_b, 16, 16, 16, __half, wmma::row_major> b[4];
        #pragma unroll
        for (int i = 0; i < 2; i++)
            wmma::load_matrix_sync(a[i], &As[(32 * wr + 16 * i) * HLD + 16 * k], HLD);
        #pragma unroll
        for (int j = 0; j < 4; j++)
            wmma::load_matrix_sync(b[j], &Bs[16 * k * HLD + 64 * wc + 16 * j], HLD);
        #pragma unroll
        for (int i = 0; i < 2; i++)
            #pragma unroll
            for (int j = 0; j < 4; j++)
                wmma::mma_sync(c[i][j], a[i], b[j], c[i][j]);
    }
    __syncthreads();

    #pragma unroll
    for (int i = 0; i < 2; i++)
        #pragma unroll
        for (int j = 0; j < 4; j++)
            wmma::store_matrix_sync(
                &Cs[(32 * wr + 16 * i) * CLD + 64 * wc + 16 * j],
                c[i][j], CLD, wmma::mem_row_major);
    __syncthreads();

    #pragma unroll
    for (int i = 0; i < 16; i++) {
        int idx = tid + 256 * i;
        int row = idx >> 5, c4 = idx & 31;
        int n = base + row;
        if (n < NN) {
            float4 v = *reinterpret_cast<const float4*>(&Cs[row * CLD + 4 * c4]);
            __half2 p01 = __floats2half2_rn(v.x, v.y);
            __half2 p23 = __floats2half2_rn(v.z, v.w);
            uint2 pk;
            pk.x = *reinterpret_cast<unsigned*>(&p01);
            pk.y = *reinterpret_cast<unsigned*>(&p23);
            *reinterpret_cast<uint2*>(&g_feath[n * F + 4 * c4]) = pk;
        }
    }
}

// ---------------- fused softmax + aggregation + next-layer scores ----------
// One warp per dst node, cooperative weights, fp16 gather, warp-uniform
// early breaks trim zero-weight padding work. Epilogue emits next layer's
// el/er (double-buffered) from the in-register output.
__global__ __launch_bounds__(256) void gat_agg_kernel(
    const int* __restrict__ src,
    const float* __restrict__ hres,
    float* __restrict__ out,
    int rbuf, int nslot, int do_act, int do_mean)
{
    const int gw = (blockIdx.x * blockDim.x + threadIdx.x) >> 5;
    if (gw >= NN) return;
    const int lane = threadIdx.x & 31;
    const int n = gw;
    const int e0 = g_rowptr[n];
    const int e1 = g_rowptr[n + 1];
    const int g = lane >> 3;
    const int p = lane & 7;
    const int shfl_base = lane & 24;
    const float* elr = g_el[rbuf];
    const float ern = g_er[rbuf][n * 4 + g];

    float ssum = 0.f;
    float4 acc = make_float4(0.f, 0.f, 0.f, 0.f);
    const uint2* feat8 = reinterpret_cast<const uint2*>(g_feath);

    for (int basee = e0; basee < e1; basee += 32) {
        int idx = basee + lane;
        int sw = (idx < e1) ? __ldg(&src[idx]) : 0;
        int lim = e1 - basee;
        if (lim > 32) lim = 32;

        float wv[4];
        #pragma unroll
        for (int k = 0; k < 4; k++) {
            if (8 * k >= lim) break;               // warp-uniform
            int jj = 8 * k + p;
            int s = __shfl_sync(0xffffffffu, sw, jj);
            float e = __ldg(&elr[s * 4 + g]) + ern;
            e = (e > 0.f) ? e : 0.2f * e;          // leaky_relu(0.2)
            float wgt = __expf(e);
            wgt = (jj < lim) ? wgt : 0.f;
            wv[k] = wgt;
            ssum += wgt;
        }

        #pragma unroll
        for (int k = 0; k < 4; k++) {
            int rem = lim - 8 * k;
            if (rem <= 0) break;                   // warp-uniform
            int pe = (rem < 8) ? rem : 8;
            #pragma unroll
            for (int p2 = 0; p2 < 8; p2++) {
                if (p2 >= pe) break;               // warp-uniform tail trim
                int jj = 8 * k + p2;
                int s = __shfl_sync(0xffffffffu, sw, jj);
                float wgt = __shfl_sync(0xffffffffu, wv[k], shfl_base + p2);
                uint2 pk = __ldg(&feat8[s * 32 + lane]);
                float2 f01 = __half22float2(*reinterpret_cast<__half2*>(&pk.x));
                float2 f23 = __half22float2(*reinterpret_cast<__half2*>(&pk.y));
                acc.x = fmaf(wgt, f01.x, acc.x);
                acc.y = fmaf(wgt, f01.y, acc.y);
                acc.z = fmaf(wgt, f23.x, acc.z);
                acc.w = fmaf(wgt, f23.y, acc.w);
            }
        }
    }

    ssum += __shfl_xor_sync(0xffffffffu, ssum, 1);
    ssum += __shfl_xor_sync(0xffffffffu, ssum, 2);
    ssum += __shfl_xor_sync(0xffffffffu, ssum, 4);

    float inv = (e1 > e0) ? (1.f / ssum) : 0.f;
    float4 o = make_float4(acc.x * inv, acc.y * inv, acc.z * inv, acc.w * inv);

    if (hres) {
        float4 rr = __ldg(&reinterpret_cast<const float4*>(hres)[n * 32 + lane]);
        o.x += rr.x; o.y += rr.y; o.z += rr.z; o.w += rr.w;
    }
    if (do_act) {  // ELU(alpha=1)
        o.x = (o.x > 0.f) ? o.x : expm1f(o.x);
        o.y = (o.y > 0.f) ? o.y : expm1f(o.y);
        o.z = (o.z > 0.f) ? o.z : expm1f(o.z);
        o.w = (o.w > 0.f) ? o.w : expm1f(o.w);
    }

    if (do_mean) {
        o.x += __shfl_xor_sync(0xffffffffu, o.x, 8);
        o.y += __shfl_xor_sync(0xffffffffu, o.y, 8);
        o.z += __shfl_xor_sync(0xffffffffu, o.z, 8);
        o.w += __shfl_xor_sync(0xffffffffu, o.w, 8);
        o.x += __shfl_xor_sync(0xffffffffu, o.x, 16);
        o.y += __shfl_xor_sync(0xffffffffu, o.y, 16);
        o.z += __shfl_xor_sync(0xffffffffu, o.z, 16);
        o.w += __shfl_xor_sync(0xffffffffu, o.w, 16);
        if (lane < 8) {
            reinterpret_cast<float4*>(out)[n * 8 + lane] =
                make_float4(o.x * 0.25f, o.y * 0.25f, o.z * 0.25f, o.w * 0.25f);
        }
        return;
    }

    reinterpret_cast<float4*>(out)[n * 32 + lane] = o;

    // ---- epilogue: next-layer el/er from in-register output ----
    {
        const float4* wl4 = reinterpret_cast<const float4*>(g_wl[nslot]);
        const float4* wr4 = reinterpret_cast<const float4*>(g_wr[nslot]);
        float pel[4], per_[4];
        #pragma unroll
        for (int h = 0; h < 4; h++) {
            float4 a = __ldg(&wl4[h * 32 + lane]);
            pel[h] = fmaf(o.x, a.x, fmaf(o.y, a.y, fmaf(o.z, a.z, o.w * a.w)));
            float4 b = __ldg(&wr4[h * 32 + lane]);
            per_[h] = fmaf(o.x, b.x, fmaf(o.y, b.y, fmaf(o.z, b.z, o.w * b.w)));
        }
        #pragma unroll
        for (int off = 16; off > 0; off >>= 1) {
            #pragma unroll
            for (int h = 0; h < 4; h++) {
                pel[h] += __shfl_xor_sync(0xffffffffu, pel[h], off);
                per_[h] += __shfl_xor_sync(0xffffffffu, per_[h], off);
            }
        }
        if (lane == 0) {
            int wbuf = rbuf ^ 1;
            *reinterpret_cast<float4*>(&g_el[wbuf][n * 4]) =
                make_float4(pel[0], pel[1], pel[2], pel[3]);
            *reinterpret_cast<float4*>(&g_er[wbuf][n * 4]) =
                make_float4(per_[0], per_[1], per_[2], per_[3]);
        }
    }
}

// ---------------- launcher --------------------------------------------------
extern "C" void kernel_launch(void* const* d_in, const int* in_sizes, int n_in,
                              void* d_out, int out_size)
{
    const float* x   = (const float*)d_in[0];
    const int*   src = (const int*)d_in[1];
    const int*   dst = (const int*)d_in[2];
    const float* W0  = (const float*)d_in[3];
    const float* al0 = (const float*)d_in[4];
    const float* ar0 = (const float*)d_in[5];
    const float* W1  = (const float*)d_in[6];
    const float* al1 = (const float*)d_in[7];
    const float* ar1 = (const float*)d_in[8];
    const float* W2  = (const float*)d_in[9];
    const float* al2 = (const float*)d_in[10];
    const float* ar2 = (const float*)d_in[11];
    float* out = (float*)d_out;

    float *h1 = nullptr, *h2 = nullptr;
    cudaGetSymbolAddress((void**)&h1, g_h1);
    cudaGetSymbolAddress((void**)&h2, g_h2);

    const int mma_smem    = 2 * MT * HLD * (int)sizeof(__half);  // 69632 B
    const int scores_smem = F * SPAD * (int)sizeof(float);       // 33280 B
    static int smem_set = 0;
    if (!smem_set) {
        cudaFuncSetAttribute(mma_kernel,
                             cudaFuncAttributeMaxDynamicSharedMemorySize, mma_smem);
        smem_set = 1;
    }

    wprep_kernel<<<3, 256>>>(W0, al0, ar0, W1, al1, ar1, W2, al2, ar2);
    rowptr_scores_kernel<<<SCAT_GRID + SCORES_GRID, 256, scores_smem>>>(dst, x);

    // layer 0: agg reads buf0, writes buf1 (next slot 1)
    mma_kernel<<<MMA_GRID, 256, mma_smem>>>(x, W0);
    gat_agg_kernel<<<AGG_GRID, 256>>>(src, nullptr, h1, 0, 1, 1, 0);

    // layer 1: agg reads buf1, writes buf0 (next slot 2)
    mma_kernel<<<MMA_GRID, 256, mma_smem>>>(h1, W1);
    gat_agg_kernel<<<AGG_GRID, 256>>>(src, h1, h2, 1, 2, 1, 0);

    // layer 2: agg reads buf0, mean over heads
    mma_kernel<<<MMA_GRID, 256, mma_smem>>>(h2, W2);
    gat_agg_kernel<<<AGG_GRID, 256>>>(src, h2, out, 0, 0, 0, 1);
}